// round 12
// baseline (speedup 1.0000x reference)
#include <cuda_runtime.h>
#include <cuda_bf16.h>

// Nearest-codeword quantization, uniform sorted 16-entry codebook.
// out[i] = argmin_c |x[i] - c|, tie toward the LOWER codeword.
//
// R12 = R8 body (best: coalesced ILP=4, front-batched loads, warp-vote
// guard) made PERSISTENT: grid = 152 SMs x 6 blocks = 912, grid-stride loop
// (~18 iterations/block). Eliminates ~18 wave transitions (T_wave_trans +
// per-wave CTA-start L1tex ramp) of the 16384-block launch; the LDG pipeline
// stays primed across iterations.
//
// Hot path per element (branchless): t = fma(x,inv,b0); tc = clamp(t,0,15);
// tr = rintf(tc); val = fma(tr,step,c0); maxd = fmax(maxd,|tc-tr|).
// ONE __any_sync vote per float4 routes the warp to an exact recompute
// (true codebook via __ldg, reference tie-break) when any lane is within
// EPS=1e-4 (index space) of a midpoint (~2.5% of warp-iterations).
// val is <=1 ulp from the stored linspace codeword (rel_err ~7e-8, tol 1e-3).

#define K_CB 16

__global__ void __launch_bounds__(256)
quant_uniform_kernel(const float4* __restrict__ x,
                     const float*  __restrict__ cb,
                     float4* __restrict__ out,
                     int n4)
{
    const float c0 = __ldg(cb);
    const float cK = __ldg(cb + K_CB - 1);
    const float step     = (cK - c0) * (1.0f / (float)(K_CB - 1));
    const float inv_step = (float)(K_CB - 1) / (cK - c0);
    const float b0 = -c0 * inv_step;
    const float TH = 0.5f - 1e-4f;      // guard threshold in index space

    const int tid    = threadIdx.x;
    const int bdim   = blockDim.x;                 // 256
    const int stride = gridDim.x * bdim * 4;       // grid-stride (float4)

    int base = blockIdx.x * (bdim * 4) + tid;

    // Main persistent loop: n4 % (bdim*4) == 0 for this problem, so every
    // iteration with base in range is a full 4-chunk iteration.
    for (; base + 3 * bdim < n4; base += stride) {
        // 4 fully-coalesced independent LDG.128, front-batched.
        float4 vv[4];
        vv[0] = x[base + 0 * bdim];
        vv[1] = x[base + 1 * bdim];
        vv[2] = x[base + 2 * bdim];
        vv[3] = x[base + 3 * bdim];

#pragma unroll
        for (int u = 0; u < 4; u++) {
            float4 r;
            const float* vp = reinterpret_cast<const float*>(&vv[u]);
            float* rp = reinterpret_cast<float*>(&r);

            float maxd = 0.0f;
#pragma unroll
            for (int j = 0; j < 4; j++) {
                float xv = vp[j];
                float t  = fmaf(xv, inv_step, b0);
                float tc = fminf(fmaxf(t, 0.0f), (float)(K_CB - 1));
                float tr = rintf(tc);
                rp[j] = fmaf(tr, step, c0);
                maxd = fmaxf(maxd, fabsf(tc - tr));   // FMNMX with |.|
            }

            // One vote per float4: does ANY lane need the exact path?
            if (__any_sync(0xFFFFFFFFu, maxd >= TH)) {
#pragma unroll
                for (int j = 0; j < 4; j++) {
                    float xv = vp[j];
                    float t  = fmaf(xv, inv_step, b0);
                    int k = min(max(__float2int_rd(t), 0), K_CB - 2);
                    float lo = __ldg(cb + k);
                    float hi = __ldg(cb + k + 1);
                    rp[j] = (fabsf(xv - lo) <= fabsf(xv - hi)) ? lo : hi;
                }
            }

            out[base + u * bdim] = r;
        }
    }

    // Defensive tail (not taken when n4 % (bdim*4) == 0): exact scalar path.
    for (int u = 0; u < 4; u++) {
        int idx = base + u * bdim;
        if (idx >= n4) break;
        float4 v = x[idx];
        float4 r;
        const float* vp = reinterpret_cast<const float*>(&v);
        float* rp = reinterpret_cast<float*>(&r);
#pragma unroll
        for (int j = 0; j < 4; j++) {
            float xv = vp[j];
            float t  = fmaf(xv, inv_step, b0);
            int k = min(max(__float2int_rd(t), 0), K_CB - 2);
            float lo = __ldg(cb + k);
            float hi = __ldg(cb + k + 1);
            rp[j] = (fabsf(xv - lo) <= fabsf(xv - hi)) ? lo : hi;
        }
        out[idx] = r;
    }
}

extern "C" void kernel_launch(void* const* d_in, const int* in_sizes, int n_in,
                              void* d_out, int out_size)
{
    const float* x  = (const float*)d_in[0];
    const float* cb = (const float*)d_in[1];
    float* out = (float*)d_out;

    int n  = in_sizes[0];         // 8192*8192 = 67,108,864
    int n4 = n >> 2;              // 16,777,216 float4

    const int threads = 256;
    // Persistent: GB300 has 152 SMs; ~6 CTAs/SM at 40 regs.
    int blocks = 152 * 6;                               // 912

    quant_uniform_kernel<<<blocks, threads>>>(
        (const float4*)x, cb, (float4*)out, n4);
}

// round 13
// speedup vs baseline: 1.1273x; 1.1273x over previous
#include <cuda_runtime.h>
#include <cuda_bf16.h>

// Nearest-codeword quantization, uniform sorted 16-entry codebook.
// out[i] = argmin_c |x[i] - c|, tie toward the LOWER codeword.
//
// R13 = R8 (best: coalesced block-strided ILP=4, front-batched LDG.128,
// classic 16384-block launch) with the rare-path vote hoisted to ONE
// __any_sync per 16 elements (was 4): single maxd across all chunks, one
// branch, then 4 uninterrupted STG.128. R12's persistent variant regressed
// (loop-carried serialization) and is reverted.
//
// Hot path per element (branchless): t = fma(x,inv,b0); tc = clamp(t,0,15);
// tr = rintf(tc); val = fma(tr,step,c0); maxd = fmax(maxd,|tc-tr|).
// If any lane of the warp is within EPS=1e-4 (index space) of a midpoint
// (~10% of warp-iterations at 16 elem/thread), the whole iteration is
// recomputed exactly against the TRUE codebook values (__ldg, reference
// tie-break). val is <=1 ulp from the stored linspace codeword
// (rel_err ~7e-8, tol 1e-3).

#define K_CB 16

__global__ void __launch_bounds__(256)
quant_uniform_kernel(const float4* __restrict__ x,
                     const float*  __restrict__ cb,
                     float4* __restrict__ out,
                     int n4)
{
    const float c0 = __ldg(cb);
    const float cK = __ldg(cb + K_CB - 1);
    const float step     = (cK - c0) * (1.0f / (float)(K_CB - 1));
    const float inv_step = (float)(K_CB - 1) / (cK - c0);
    const float b0 = -c0 * inv_step;
    const float TH = 0.5f - 1e-4f;      // guard threshold in index space

    const int tid  = threadIdx.x;
    const int bdim = blockDim.x;                  // 256
    const int base = blockIdx.x * (bdim * 4) + tid;

    if (base + 3 * bdim < n4) {
        // 4 fully-coalesced independent LDG.128, front-batched.
        float4 vv[4];
        vv[0] = x[base + 0 * bdim];
        vv[1] = x[base + 1 * bdim];
        vv[2] = x[base + 2 * bdim];
        vv[3] = x[base + 3 * bdim];

        float4 rr[4];
        float maxd = 0.0f;

#pragma unroll
        for (int u = 0; u < 4; u++) {
            const float* vp = reinterpret_cast<const float*>(&vv[u]);
            float* rp = reinterpret_cast<float*>(&rr[u]);
#pragma unroll
            for (int j = 0; j < 4; j++) {
                float xv = vp[j];
                float t  = fmaf(xv, inv_step, b0);
                float tc = fminf(fmaxf(t, 0.0f), (float)(K_CB - 1));
                float tr = rintf(tc);
                rp[j] = fmaf(tr, step, c0);
                maxd = fmaxf(maxd, fabsf(tc - tr));   // FMNMX with |.|
            }
        }

        // ONE vote per 16 elements: does ANY lane need the exact path?
        if (__any_sync(0xFFFFFFFFu, maxd >= TH)) {
#pragma unroll
            for (int u = 0; u < 4; u++) {
                const float* vp = reinterpret_cast<const float*>(&vv[u]);
                float* rp = reinterpret_cast<float*>(&rr[u]);
#pragma unroll
                for (int j = 0; j < 4; j++) {
                    float xv = vp[j];
                    float t  = fmaf(xv, inv_step, b0);
                    int k = min(max(__float2int_rd(t), 0), K_CB - 2);
                    float lo = __ldg(cb + k);
                    float hi = __ldg(cb + k + 1);
                    rp[j] = (fabsf(xv - lo) <= fabsf(xv - hi)) ? lo : hi;
                }
            }
        }

        // Uninterrupted store burst.
        out[base + 0 * bdim] = rr[0];
        out[base + 1 * bdim] = rr[1];
        out[base + 2 * bdim] = rr[2];
        out[base + 3 * bdim] = rr[3];
    } else {
        // Tail (not taken for 8192x8192): always-exact scalar path.
        for (int u = 0; u < 4; u++) {
            int idx = base + u * bdim;
            if (idx >= n4) break;
            float4 v = x[idx];
            float4 r;
            const float* vp = reinterpret_cast<const float*>(&v);
            float* rp = reinterpret_cast<float*>(&r);
#pragma unroll
            for (int j = 0; j < 4; j++) {
                float xv = vp[j];
                float t  = fmaf(xv, inv_step, b0);
                int k = min(max(__float2int_rd(t), 0), K_CB - 2);
                float lo = __ldg(cb + k);
                float hi = __ldg(cb + k + 1);
                rp[j] = (fabsf(xv - lo) <= fabsf(xv - hi)) ? lo : hi;
            }
            out[idx] = r;
        }
    }
}

extern "C" void kernel_launch(void* const* d_in, const int* in_sizes, int n_in,
                              void* d_out, int out_size)
{
    const float* x  = (const float*)d_in[0];
    const float* cb = (const float*)d_in[1];
    float* out = (float*)d_out;

    int n  = in_sizes[0];         // 8192*8192 = 67,108,864
    int n4 = n >> 2;              // 16,777,216 float4

    const int threads = 256;
    const int per_block = threads * 4;                 // 1024 float4 / block
    int blocks = (n4 + per_block - 1) / per_block;     // 16384

    quant_uniform_kernel<<<blocks, threads>>>(
        (const float4*)x, cb, (float4*)out, n4);
}